// round 4
// baseline (speedup 1.0000x reference)
#include <cuda_runtime.h>
#include <cuda_bf16.h>

// ---------------------------------------------------------------------------
// Kernel 1: zero the full dense output (537 MB). Pure streaming store;
// this is the DRAM roofline for the whole problem.
// ---------------------------------------------------------------------------
__global__ void zero_f4_kernel(float4* __restrict__ o, long n4,
                               float* __restrict__ tail, int ntail) {
    long i = (long)blockIdx.x * blockDim.x + threadIdx.x;
    if (i < n4) o[i] = make_float4(0.f, 0.f, 0.f, 0.f);
    if (i == 0) {
        for (int t = 0; t < ntail; t++) tail[t] = 0.f;
    }
}

// ---------------------------------------------------------------------------
// Kernel 2: per-voxel PointNet MLP + scatter.
//
// Math (matching the jax reference):
//   per point p < n:  y = f_p @ W1 + b1            (4 -> 16)
//                     h = relu(LN(y; g1, be1))
//   acc = sum_p h
//   x = acc @ W2 + n*b2                            (uses linearity of the
//                                                   masked sum over W2/b2)
//   out[flat(coords)] = LN(x; g2, be2)
//
// One thread per voxel. Weights staged in shared memory (broadcast reads).
// ---------------------------------------------------------------------------
__global__ __launch_bounds__(256)
void voxel_mlp_kernel(const float*  __restrict__ features,
                      const int*    __restrict__ num_points,
                      const int*    __restrict__ coords,
                      const float*  __restrict__ W1,  const float* __restrict__ b1,
                      const float*  __restrict__ g1,  const float* __restrict__ be1,
                      const float*  __restrict__ W2,  const float* __restrict__ b2,
                      const float*  __restrict__ g2,  const float* __restrict__ be2,
                      const int*    __restrict__ p_gh,
                      const int*    __restrict__ p_gw,
                      const int*    __restrict__ p_gz,
                      float*        __restrict__ out,
                      int V, int P, long out_elems, long stride_fallback)
{
    __shared__ float sW1[64], sW2[256];
    __shared__ float sb1[16], sg1[16], sbe1[16];
    __shared__ float sb2[16], sg2[16], sbe2[16];

    const int tid = threadIdx.x;
    if (tid < 64)  sW1[tid] = W1[tid];
    if (tid < 256) sW2[tid] = W2[tid];
    if (tid < 16) {
        sb1[tid]  = b1[tid];  sg1[tid] = g1[tid];  sbe1[tid] = be1[tid];
        sb2[tid]  = b2[tid];  sg2[tid] = g2[tid];  sbe2[tid] = be2[tid];
    }
    __syncthreads();

    const int v = blockIdx.x * 256 + tid;
    if (v >= V) return;

    int n = num_points[v];
    if (n < 0) n = 0;
    if (n > P) n = P;

    // IN == 4 -> each point is exactly one float4
    const float4* f = reinterpret_cast<const float4*>(features) + (size_t)v * P;

    float acc[16];
#pragma unroll
    for (int j = 0; j < 16; j++) acc[j] = 0.f;

    for (int p = 0; p < n; p++) {
        const float4 x = f[p];
        float y[16];
#pragma unroll
        for (int j = 0; j < 16; j++) {
            float t = fmaf(x.x, sW1[j],      sb1[j]);
            t       = fmaf(x.y, sW1[16 + j], t);
            t       = fmaf(x.z, sW1[32 + j], t);
            y[j]    = fmaf(x.w, sW1[48 + j], t);
        }
        // layernorm over 16
        float mu = 0.f;
#pragma unroll
        for (int j = 0; j < 16; j++) mu += y[j];
        mu *= 0.0625f;
        float var = 0.f;
#pragma unroll
        for (int j = 0; j < 16; j++) { float d = y[j] - mu; var = fmaf(d, d, var); }
        const float inv = rsqrtf(fmaf(var, 0.0625f, 1e-5f));
#pragma unroll
        for (int j = 0; j < 16; j++) {
            float h = fmaf((y[j] - mu) * inv, sg1[j], sbe1[j]);
            acc[j] += fmaxf(h, 0.f);
        }
    }

    // Second linear: x2 = acc @ W2 + n*b2
    float x2[16];
    const float fn = (float)n;
#pragma unroll
    for (int i = 0; i < 16; i++) x2[i] = fn * sb2[i];
#pragma unroll
    for (int j = 0; j < 16; j++) {
        const float a = acc[j];
#pragma unroll
        for (int i = 0; i < 16; i++) x2[i] = fmaf(a, sW2[j * 16 + i], x2[i]);
    }

    // Final layernorm over 16
    float mu = 0.f;
#pragma unroll
    for (int i = 0; i < 16; i++) mu += x2[i];
    mu *= 0.0625f;
    float var = 0.f;
#pragma unroll
    for (int i = 0; i < 16; i++) { float d = x2[i] - mu; var = fmaf(d, d, var); }
    const float inv = rsqrtf(fmaf(var, 0.0625f, 1e-5f));

    // Scatter destination
    long flat;
    if (p_gh != nullptr) {
        const int GH = *p_gh, GW = *p_gw, GZ = *p_gz;
        const int b  = coords[4 * v + 0];
        const int ix = coords[4 * v + 1];
        const int iy = coords[4 * v + 2];
        const int iz = coords[4 * v + 3];
        flat = (((long)b * GH + ix) * GW + iy) * (long)GZ + iz;
    } else {
        flat = (long)v * stride_fallback;
    }
    const long off = flat * 16;
    if (off < 0 || off + 16 > out_elems) return;   // mode='drop'

    float4* o = reinterpret_cast<float4*>(out + off);
#pragma unroll
    for (int q = 0; q < 4; q++) {
        float4 r;
        r.x = fmaf((x2[4 * q + 0] - mu) * inv, sg2[4 * q + 0], sbe2[4 * q + 0]);
        r.y = fmaf((x2[4 * q + 1] - mu) * inv, sg2[4 * q + 1], sbe2[4 * q + 1]);
        r.z = fmaf((x2[4 * q + 2] - mu) * inv, sg2[4 * q + 2], sbe2[4 * q + 2]);
        r.w = fmaf((x2[4 * q + 3] - mu) * inv, sg2[4 * q + 3], sbe2[4 * q + 3]);
        o[q] = r;
    }
}

extern "C" void kernel_launch(void* const* d_in, const int* in_sizes, int n_in,
                              void* d_out, int out_size)
{
    // metadata order: features, num_points, coords, W1, b1, g1, be1,
    //                 W2, b2, g2, be2, batch_size, grid_h, grid_w, grid_z
    const float* features   = (const float*)d_in[0];
    const int*   num_points = (const int*)  d_in[1];
    const int*   coords     = (const int*)  d_in[2];
    const float* W1  = (const float*)d_in[3];
    const float* b1  = (const float*)d_in[4];
    const float* g1  = (const float*)d_in[5];
    const float* be1 = (const float*)d_in[6];
    const float* W2  = (const float*)d_in[7];
    const float* b2  = (const float*)d_in[8];
    const float* g2  = (const float*)d_in[9];
    const float* be2 = (const float*)d_in[10];

    const int* p_gh = nullptr;
    const int* p_gw = nullptr;
    const int* p_gz = nullptr;
    if (n_in >= 15) {
        p_gh = (const int*)d_in[12];
        p_gw = (const int*)d_in[13];
        p_gz = (const int*)d_in[14];
    }

    const int V  = in_sizes[1];                 // num_points length
    const int H  = in_sizes[4];                 // b1 length (16)
    const int IN = in_sizes[3] / H;             // W1 rows (4)
    const int P  = (in_sizes[0] / V) / IN;      // points per voxel (32)

    float* out = (float*)d_out;
    const long out_elems = (long)out_size;
    const long stride_fallback = (out_elems / 16) / (long)V;

    // 1) zero the dense output (DRAM-roofline pass)
    {
        const long n4    = out_elems / 4;
        const int  ntail = (int)(out_elems % 4);
        float* tail = out + n4 * 4;
        const long blocks = (n4 + 255) / 256;
        zero_f4_kernel<<<(unsigned)blocks, 256>>>(
            reinterpret_cast<float4*>(out), n4, tail, ntail);
    }

    // 2) per-voxel MLP + scatter (ordered after zeroing on the same stream)
    {
        const int blocks = (V + 255) / 256;
        voxel_mlp_kernel<<<blocks, 256>>>(
            features, num_points, coords,
            W1, b1, g1, be1, W2, b2, g2, be2,
            p_gh, p_gw, p_gz,
            out, V, P, out_elems, stride_fallback);
    }
}